// round 1
// baseline (speedup 1.0000x reference)
#include <cuda_runtime.h>
#include <math.h>

#define B_ROWS 1024
#define D_IN   512
#define D_H    512
#define D_OUT  256

// ---- scratch (device globals; no allocation allowed) ----
__device__ float g_Ex [B_ROWS * D_IN];   // exp(x) / exp(activated h)
__device__ float g_G  [B_ROWS * D_H];    // exp(relu(ln(h)))
__device__ float g_H  [B_ROWS * D_H];    // logsumexp outputs (pre-LN)
__device__ float g_Ew1[D_H   * D_IN];
__device__ float g_Ew2[D_H   * D_H];
__device__ float g_Ew3[D_OUT * D_H];

// ---------------------------------------------------------------------------
// elementwise exp
// ---------------------------------------------------------------------------
__global__ void exp_kernel(const float* __restrict__ in, float* __restrict__ out, int n) {
    int i = blockIdx.x * blockDim.x + threadIdx.x;
    if (i < n) out[i] = __expf(in[i]);
}

// ---------------------------------------------------------------------------
// C[m,n] = log( sum_k A[m,k] * B[n,k] ) + bias[n]
// A: M x K row-major (exp-domain activations), B: N x K row-major (exp(w))
// Tile 64x64, BK=32, 256 threads, 4x4 per-thread micro-tile.
// M, N, K all multiples of 64/64/32 here, so no bounds checks.
// ---------------------------------------------------------------------------
__global__ __launch_bounds__(256) void gemm_log_kernel(
    const float* __restrict__ A, const float* __restrict__ Bm,
    const float* __restrict__ bias, float* __restrict__ C,
    int N, int K)
{
    __shared__ float As[32 * 65];   // transposed: As[k*65 + m]
    __shared__ float Bs[32 * 65];   // transposed: Bs[k*65 + n]

    const int tid = threadIdx.x;
    const int bm  = blockIdx.y * 64;
    const int bn  = blockIdx.x * 64;
    const int ty  = tid >> 4;       // 0..15
    const int tx  = tid & 15;       // 0..15

    float acc[4][4];
#pragma unroll
    for (int i = 0; i < 4; ++i)
#pragma unroll
        for (int j = 0; j < 4; ++j) acc[i][j] = 0.0f;

    // loader mapping: 2048 floats per tile = 512 float4; thread t handles
    // float4 #t and #(t+256):  row = lin>>3 (0..63), col4 = (lin&7)*4
    const int r0  = tid >> 3;           // 0..31  (second load: r0+32)
    const int c40 = (tid & 7) << 2;     // 0,4,...,28

    const float* Aptr = A  + (size_t)(bm + r0) * K + c40;
    const float* Bptr = Bm + (size_t)(bn + r0) * K + c40;

    for (int k0 = 0; k0 < K; k0 += 32) {
        float4 va0 = *(const float4*)(Aptr + k0);
        float4 va1 = *(const float4*)(Aptr + (size_t)32 * K + k0);
        float4 vb0 = *(const float4*)(Bptr + k0);
        float4 vb1 = *(const float4*)(Bptr + (size_t)32 * K + k0);

        As[(c40 + 0) * 65 + r0     ] = va0.x;
        As[(c40 + 1) * 65 + r0     ] = va0.y;
        As[(c40 + 2) * 65 + r0     ] = va0.z;
        As[(c40 + 3) * 65 + r0     ] = va0.w;
        As[(c40 + 0) * 65 + r0 + 32] = va1.x;
        As[(c40 + 1) * 65 + r0 + 32] = va1.y;
        As[(c40 + 2) * 65 + r0 + 32] = va1.z;
        As[(c40 + 3) * 65 + r0 + 32] = va1.w;

        Bs[(c40 + 0) * 65 + r0     ] = vb0.x;
        Bs[(c40 + 1) * 65 + r0     ] = vb0.y;
        Bs[(c40 + 2) * 65 + r0     ] = vb0.z;
        Bs[(c40 + 3) * 65 + r0     ] = vb0.w;
        Bs[(c40 + 0) * 65 + r0 + 32] = vb1.x;
        Bs[(c40 + 1) * 65 + r0 + 32] = vb1.y;
        Bs[(c40 + 2) * 65 + r0 + 32] = vb1.z;
        Bs[(c40 + 3) * 65 + r0 + 32] = vb1.w;

        __syncthreads();

#pragma unroll
        for (int k = 0; k < 32; ++k) {
            float a[4], b[4];
#pragma unroll
            for (int i = 0; i < 4; ++i) a[i] = As[k * 65 + ty * 4 + i];
#pragma unroll
            for (int j = 0; j < 4; ++j) b[j] = Bs[k * 65 + tx * 4 + j];
#pragma unroll
            for (int i = 0; i < 4; ++i)
#pragma unroll
                for (int j = 0; j < 4; ++j)
                    acc[i][j] = fmaf(a[i], b[j], acc[i][j]);
        }
        __syncthreads();
    }

#pragma unroll
    for (int i = 0; i < 4; ++i) {
        int row = bm + ty * 4 + i;
#pragma unroll
        for (int j = 0; j < 4; ++j) {
            int col = bn + tx * 4 + j;
            C[(size_t)row * N + col] = __logf(acc[i][j]) + bias[col];
        }
    }
}

// ---------------------------------------------------------------------------
// trop_layernorm (median / IQR via full bitonic sort of the 512-row) +
// weight/bias + ReLU + exp (exp feeds the next exp-domain GEMM).
// One block (256 threads) per row.
//   median = sorted[255]                      (lower middle, n=512)
//   q25 at pos 0.25*511 = 127.75 -> s[127] + 0.75*(s[128]-s[127])
//   q75 at pos 0.75*511 = 383.25 -> s[383] + 0.25*(s[384]-s[383])
// ---------------------------------------------------------------------------
__global__ __launch_bounds__(256) void ln_relu_exp_kernel(
    const float* __restrict__ H, const float* __restrict__ lw,
    const float* __restrict__ lb, float* __restrict__ G)
{
    __shared__ float sv[512];
    __shared__ float ss[512];
    const int row = blockIdx.x;
    const int tid = threadIdx.x;
    const float* h = H + (size_t)row * 512;

#pragma unroll
    for (int l = 0; l < 2; ++l) {
        int i = tid + l * 256;
        float v = h[i];
        sv[i] = v;
        ss[i] = v;
    }
    __syncthreads();

    // bitonic sort, ascending
    for (int k = 2; k <= 512; k <<= 1) {
        for (int j = k >> 1; j > 0; j >>= 1) {
#pragma unroll
            for (int l = 0; l < 2; ++l) {
                int i = tid + l * 256;
                int ixj = i ^ j;
                if (ixj > i) {
                    float a = ss[i], b = ss[ixj];
                    bool sw = ((i & k) == 0) ? (a > b) : (a < b);
                    if (sw) { ss[i] = b; ss[ixj] = a; }
                }
            }
            __syncthreads();
        }
    }

    float med = ss[255];
    float q25 = fmaf(0.75f, ss[128] - ss[127], ss[127]);
    float q75 = fmaf(0.25f, ss[384] - ss[383], ss[383]);
    float iqr = fmaxf(q75 - q25, 1e-6f);
    float inv = 1.0f / iqr;

#pragma unroll
    for (int l = 0; l < 2; ++l) {
        int i = tid + l * 256;
        float y = (sv[i] - med) * inv * lw[i] + lb[i];
        y = fmaxf(y, 0.0f);
        G[(size_t)row * 512 + i] = __expf(y);
    }
}

// ---------------------------------------------------------------------------
// launch
// inputs: 0:x 1:w1 2:b1 3:ln1_w 4:ln1_b 5:w2 6:b2 7:ln2_w 8:ln2_b 9:w3 10:b3
// ---------------------------------------------------------------------------
extern "C" void kernel_launch(void* const* d_in, const int* in_sizes, int n_in,
                              void* d_out, int out_size)
{
    const float* x     = (const float*)d_in[0];
    const float* w1    = (const float*)d_in[1];
    const float* b1    = (const float*)d_in[2];
    const float* ln1_w = (const float*)d_in[3];
    const float* ln1_b = (const float*)d_in[4];
    const float* w2    = (const float*)d_in[5];
    const float* b2    = (const float*)d_in[6];
    const float* ln2_w = (const float*)d_in[7];
    const float* ln2_b = (const float*)d_in[8];
    const float* w3    = (const float*)d_in[9];
    const float* b3    = (const float*)d_in[10];
    float* out = (float*)d_out;

    float *pEx, *pG, *pH, *pEw1, *pEw2, *pEw3;
    cudaGetSymbolAddress((void**)&pEx,  g_Ex);
    cudaGetSymbolAddress((void**)&pG,   g_G);
    cudaGetSymbolAddress((void**)&pH,   g_H);
    cudaGetSymbolAddress((void**)&pEw1, g_Ew1);
    cudaGetSymbolAddress((void**)&pEw2, g_Ew2);
    cudaGetSymbolAddress((void**)&pEw3, g_Ew3);

    // exp-domain operands
    exp_kernel<<<(B_ROWS * D_IN + 255) / 256, 256>>>(x,  pEx,  B_ROWS * D_IN);
    exp_kernel<<<(D_H * D_IN    + 255) / 256, 256>>>(w1, pEw1, D_H * D_IN);
    exp_kernel<<<(D_H * D_H     + 255) / 256, 256>>>(w2, pEw2, D_H * D_H);
    exp_kernel<<<(D_OUT * D_H   + 255) / 256, 256>>>(w3, pEw3, D_OUT * D_H);

    // layer 1: h = log(Ex . Ew1^T) + b1
    gemm_log_kernel<<<dim3(D_H / 64, B_ROWS / 64), 256>>>(pEx, pEw1, b1, pH, D_H, D_IN);
    // LN + relu + exp
    ln_relu_exp_kernel<<<B_ROWS, 256>>>(pH, ln1_w, ln1_b, pG);

    // layer 2
    gemm_log_kernel<<<dim3(D_H / 64, B_ROWS / 64), 256>>>(pG, pEw2, b2, pH, D_H, D_H);
    ln_relu_exp_kernel<<<B_ROWS, 256>>>(pH, ln2_w, ln2_b, pEx);  // reuse Ex as G2

    // layer 3 -> output
    gemm_log_kernel<<<dim3(D_OUT / 64, B_ROWS / 64), 256>>>(pEx, pEw3, b3, out, D_OUT, D_H);
}

// round 8
// speedup vs baseline: 1.0308x; 1.0308x over previous
#include <cuda_runtime.h>
#include <cuda_bf16.h>
#include <mma.h>
#include <cstdint>
#include <math.h>

using namespace nvcuda;

#define B_ROWS 1024
#define D_IN   512
#define D_H    512
#define D_OUT  256

// ---------------- scratch (device globals; no allocation allowed) ----------
__device__ __nv_bfloat16 g_AH[B_ROWS * D_IN];   // activation hi (ping)
__device__ __nv_bfloat16 g_AL[B_ROWS * D_IN];   // activation lo (ping)
__device__ __nv_bfloat16 g_GH[B_ROWS * D_H];    // activation hi (pong)
__device__ __nv_bfloat16 g_GL[B_ROWS * D_H];    // activation lo (pong)
__device__ float         g_H [B_ROWS * D_H];    // pre-LN fp32
__device__ __nv_bfloat16 g_W1H[D_H * D_IN];
__device__ __nv_bfloat16 g_W1L[D_H * D_IN];
__device__ __nv_bfloat16 g_W2H[D_H * D_H];
__device__ __nv_bfloat16 g_W2L[D_H * D_H];
__device__ __nv_bfloat16 g_W3H[D_OUT * D_H];
__device__ __nv_bfloat16 g_W3L[D_OUT * D_H];

// ---------------------------------------------------------------------------
// elementwise: e = exp(v); hi = bf16(e); lo = bf16(e - hi)
// ---------------------------------------------------------------------------
__device__ __forceinline__ void exp_split1(float v, __nv_bfloat16* hi, __nv_bfloat16* lo) {
    float e = __expf(v);
    __nv_bfloat16 h = __float2bfloat16(e);
    *hi = h;
    *lo = __float2bfloat16(e - __bfloat162float(h));
}

__global__ void exp_split_kernel(const float* __restrict__ in,
                                 __nv_bfloat16* __restrict__ hi,
                                 __nv_bfloat16* __restrict__ lo, int n) {
    int i = blockIdx.x * blockDim.x + threadIdx.x;
    if (i < n) exp_split1(in[i], hi + i, lo + i);
}

// all three weight matrices in one launch
__global__ void exp_split_w_kernel(const float* __restrict__ w1,
                                   const float* __restrict__ w2,
                                   const float* __restrict__ w3,
                                   __nv_bfloat16* __restrict__ w1h, __nv_bfloat16* __restrict__ w1l,
                                   __nv_bfloat16* __restrict__ w2h, __nv_bfloat16* __restrict__ w2l,
                                   __nv_bfloat16* __restrict__ w3h, __nv_bfloat16* __restrict__ w3l) {
    int i = blockIdx.x * blockDim.x + threadIdx.x;
    const int n1 = D_H * D_IN, n2 = n1 + D_H * D_H, n3 = n2 + D_OUT * D_H;
    if (i < n1)       exp_split1(w1[i],      w1h + i,        w1l + i);
    else if (i < n2)  exp_split1(w2[i - n1], w2h + (i - n1), w2l + (i - n1));
    else if (i < n3)  exp_split1(w3[i - n2], w3h + (i - n2), w3l + (i - n2));
}

// ---------------------------------------------------------------------------
// WMMA (HMMA) GEMM + log + bias:  C[m,n] = log( sum_k A[m,k]*B[n,k] ) + bias[n]
// A: M x K row-major (exp-domain, hi/lo bf16), B: N x K row-major (hi/lo bf16).
// fp32 accumulate of AhiBhi + AhiBlo + AloBhi  (lo*lo dropped, O(2^-16) rel).
// CTA tile 128(M) x 64(N), 8 warps in 4x2, warp tile 32x32 (2x2 wmma frags),
// BK=32 smem-staged.  B loads as col_major K x N fragment straight from [N,K].
// ---------------------------------------------------------------------------
#define LDA 40          // bf16 ldm for staged 32-wide tiles (8-elem aligned)
#define LDC 68          // f32 ldm for epilogue tile

__global__ __launch_bounds__(256) void gemm_wmma_log_kernel(
    const __nv_bfloat16* __restrict__ Ahi, const __nv_bfloat16* __restrict__ Alo,
    const __nv_bfloat16* __restrict__ Bhi, const __nv_bfloat16* __restrict__ Blo,
    const float* __restrict__ bias, float* __restrict__ C, int N, int K)
{
    extern __shared__ char smem[];
    __nv_bfloat16* sAh = (__nv_bfloat16*)smem;          // 128*LDA
    __nv_bfloat16* sAl = sAh + 128 * LDA;
    __nv_bfloat16* sBh = sAl + 128 * LDA;               // 64*LDA
    __nv_bfloat16* sBl = sBh + 64 * LDA;
    float* sC = (float*)smem;                           // reused in epilogue: 128*LDC

    const int tid = threadIdx.x;
    const int wid = tid >> 5;
    const int bm = blockIdx.y * 128;
    const int bn = blockIdx.x * 64;
    const int wm = (wid >> 1) * 32;      // warp row offset in CTA tile
    const int wn = (wid & 1) * 32;       // warp col offset

    wmma::fragment<wmma::accumulator, 16, 16, 16, float> c[2][2];
#pragma unroll
    for (int i = 0; i < 2; ++i)
#pragma unroll
        for (int j = 0; j < 2; ++j) wmma::fill_fragment(c[i][j], 0.0f);

    // loader geometry
    const int ar = tid >> 1, ah2 = tid & 1;   // A: row 0..127, 16-col half
    const int br = tid >> 2, bq = tid & 3;    // B: row 0..63, 8-col quarter

    for (int k0 = 0; k0 < K; k0 += 32) {
        // stage A (128x32) hi/lo: 2 x uint4 per thread per tile
        {
            const __nv_bfloat16* gah = Ahi + (size_t)(bm + ar) * K + k0 + ah2 * 16;
            const __nv_bfloat16* gal = Alo + (size_t)(bm + ar) * K + k0 + ah2 * 16;
            __nv_bfloat16* dsth = sAh + ar * LDA + ah2 * 16;
            __nv_bfloat16* dstl = sAl + ar * LDA + ah2 * 16;
            *(uint4*)(dsth)     = *(const uint4*)(gah);
            *(uint4*)(dsth + 8) = *(const uint4*)(gah + 8);
            *(uint4*)(dstl)     = *(const uint4*)(gal);
            *(uint4*)(dstl + 8) = *(const uint4*)(gal + 8);
        }
        // stage B (64x32) hi/lo: 1 x uint4 per thread per tile
        {
            const __nv_bfloat16* gbh = Bhi + (size_t)(bn + br) * K + k0 + bq * 8;
            const __nv_bfloat16* gbl = Blo + (size_t)(bn + br) * K + k0 + bq * 8;
            *(uint4*)(sBh + br * LDA + bq * 8) = *(const uint4*)(gbh);
            *(uint4*)(sBl + br * LDA + bq * 8) = *(const uint4*)(gbl);
        }
        __syncthreads();

#pragma unroll
        for (int ks = 0; ks < 32; ks += 16) {
            wmma::fragment<wmma::matrix_a, 16, 16, 16, __nv_bfloat16, wmma::row_major> ahf[2], alf[2];
            wmma::fragment<wmma::matrix_b, 16, 16, 16, __nv_bfloat16, wmma::col_major> bhf[2], blf[2];
#pragma unroll
            for (int i = 0; i < 2; ++i) {
                wmma::load_matrix_sync(ahf[i], sAh + (wm + 16 * i) * LDA + ks, LDA);
                wmma::load_matrix_sync(alf[i], sAl + (wm + 16 * i) * LDA + ks, LDA);
            }
#pragma unroll
            for (int j = 0; j < 2; ++j) {
                wmma::load_matrix_sync(bhf[j], sBh + (wn + 16 * j) * LDA + ks, LDA);
                wmma::load_matrix_sync(blf[j], sBl + (wn + 16 * j) * LDA + ks, LDA);
            }
#pragma unroll
            for (int i = 0; i < 2; ++i)
#pragma unroll
                for (int j = 0; j < 2; ++j) {
                    wmma::mma_sync(c[i][j], ahf[i], bhf[j], c[i][j]);
                    wmma::mma_sync(c[i][j], ahf[i], blf[j], c[i][j]);
                    wmma::mma_sync(c[i][j], alf[i], bhf[j], c[i][j]);
                }
        }
        __syncthreads();   // all frag reads done before next stage overwrite
    }

    // epilogue: frags -> smem -> log+bias -> global (coalesced)
#pragma unroll
    for (int i = 0; i < 2; ++i)
#pragma unroll
        for (int j = 0; j < 2; ++j)
            wmma::store_matrix_sync(sC + (wm + 16 * i) * LDC + (wn + 16 * j),
                                    c[i][j], LDC, wmma::mem_row_major);
    __syncthreads();

    {
        const int r = tid >> 1;            // 0..127
        const int h = tid & 1;             // column half (32 each)
        const float* src = sC + r * LDC + h * 32;
        float* dst = C + (size_t)(bm + r) * N + bn + h * 32;
        const float* bi = bias + bn + h * 32;
#pragma unroll
        for (int cidx = 0; cidx < 32; ++cidx)
            dst[cidx] = __logf(src[cidx]) + bi[cidx];
    }
}

// ---------------------------------------------------------------------------
// trop_layernorm (bitonic sort for median/IQR) + relu + exp + hi/lo split.
// One 256-thread block per row of 512.
//   median = s[255];  q25 = s[127]+0.75*(s[128]-s[127]);  q75 = s[383]+0.25*(s[384]-s[383])
// ---------------------------------------------------------------------------
__global__ __launch_bounds__(256) void ln_relu_expsplit_kernel(
    const float* __restrict__ H, const float* __restrict__ lw,
    const float* __restrict__ lb,
    __nv_bfloat16* __restrict__ Ghi, __nv_bfloat16* __restrict__ Glo)
{
    __shared__ float sv[512];
    __shared__ float ss[512];
    const int row = blockIdx.x;
    const int tid = threadIdx.x;
    const float* h = H + (size_t)row * 512;

#pragma unroll
    for (int l = 0; l < 2; ++l) {
        int i = tid + l * 256;
        float v = h[i];
        sv[i] = v;
        ss[i] = v;
    }
    __syncthreads();

    for (int k = 2; k <= 512; k <<= 1) {
        for (int j = k >> 1; j > 0; j >>= 1) {
#pragma unroll
            for (int l = 0; l < 2; ++l) {
                int i = tid + l * 256;
                int ixj = i ^ j;
                if (ixj > i) {
                    float a = ss[i], b = ss[ixj];
                    bool sw = ((i & k) == 0) ? (a > b) : (a < b);
                    if (sw) { ss[i] = b; ss[ixj] = a; }
                }
            }
            __syncthreads();
        }
    }

    float med = ss[255];
    float q25 = fmaf(0.75f, ss[128] - ss[127], ss[127]);
    float q75 = fmaf(0.25f, ss[384] - ss[383], ss[383]);
    float inv = 1.0f / fmaxf(q75 - q25, 1e-6f);

#pragma unroll
    for (int l = 0; l < 2; ++l) {
        int i = tid + l * 256;
        float y = (sv[i] - med) * inv * lw[i] + lb[i];
        y = fmaxf(y, 0.0f);
        exp_split1(y, Ghi + (size_t)row * 512 + i, Glo + (size_t)row * 512 + i);
    }
}

// ---------------------------------------------------------------------------
// launch — inputs: 0:x 1:w1 2:b1 3:ln1_w 4:ln1_b 5:w2 6:b2 7:ln2_w 8:ln2_b 9:w3 10:b3
// ---------------------------------------------------------------------------
extern "C" void kernel_launch(void* const* d_in, const int* in_sizes, int n_in,
                              void* d_out, int out_size)
{
    const float* x     = (const float*)d_in[0];
    const float* w1    = (const float*)d_in[1];
    const float* b1    = (const float*)d_in[2];
    const float* ln1_w = (const float*)d_in[3];
    const float* ln1_b = (const float*)d_in[4];
    const float* w2    = (const float*)d_in[5];
    const float* b2    = (const float*)d_in[6];
    const float* ln2_w = (const float*)d_in[7];
    const float* ln2_b = (const float*)d_in[8];
    const float* w3    = (const float*)d_in[9];
    const float* b3    = (const float*)d_in[10];
    float* out = (float*)d_out;

    __nv_bfloat16 *pAH, *pAL, *pGH, *pGL, *pW1H, *pW1L, *pW2H, *pW2L, *pW3H, *pW3L;
    float* pH;
    cudaGetSymbolAddress((void**)&pAH, g_AH);
    cudaGetSymbolAddress((void**)&pAL, g_AL);
    cudaGetSymbolAddress((void**)&pGH, g_GH);
    cudaGetSymbolAddress((void**)&pGL, g_GL);
    cudaGetSymbolAddress((void**)&pH,  g_H);
    cudaGetSymbolAddress((void**)&pW1H, g_W1H);
    cudaGetSymbolAddress((void**)&pW1L, g_W1L);
    cudaGetSymbolAddress((void**)&pW2H, g_W2H);
    cudaGetSymbolAddress((void**)&pW2L, g_W2L);
    cudaGetSymbolAddress((void**)&pW3H, g_W3H);
    cudaGetSymbolAddress((void**)&pW3L, g_W3L);

    // smem: stages = (128+64)*LDA*2 tiles*2B = 30720 B; epilogue = 128*LDC*4 = 34816 B
    const int SMEM_SZ = 128 * LDC * 4;   // 34816 (covers both uses)
    cudaFuncSetAttribute(gemm_wmma_log_kernel,
                         cudaFuncAttributeMaxDynamicSharedMemorySize, SMEM_SZ);

    // exp-domain operands (hi/lo split)
    exp_split_kernel<<<(B_ROWS * D_IN + 255) / 256, 256>>>(x, pAH, pAL, B_ROWS * D_IN);
    {
        int nw = D_H * D_IN + D_H * D_H + D_OUT * D_H;
        exp_split_w_kernel<<<(nw + 255) / 256, 256>>>(w1, w2, w3,
                                                      pW1H, pW1L, pW2H, pW2L, pW3H, pW3L);
    }

    // layer 1
    gemm_wmma_log_kernel<<<dim3(D_H / 64, B_ROWS / 128), 256, SMEM_SZ>>>(
        pAH, pAL, pW1H, pW1L, b1, pH, D_H, D_IN);
    ln_relu_expsplit_kernel<<<B_ROWS, 256>>>(pH, ln1_w, ln1_b, pGH, pGL);

    // layer 2
    gemm_wmma_log_kernel<<<dim3(D_H / 64, B_ROWS / 128), 256, SMEM_SZ>>>(
        pGH, pGL, pW2H, pW2L, b2, pH, D_H, D_H);
    ln_relu_expsplit_kernel<<<B_ROWS, 256>>>(pH, ln2_w, ln2_b, pAH, pAL);

    // layer 3 -> output
    gemm_wmma_log_kernel<<<dim3(D_OUT / 64, B_ROWS / 128), 256, SMEM_SZ>>>(
        pAH, pAL, pW3H, pW3L, b3, out, D_OUT, D_H);
}

// round 13
// speedup vs baseline: 1.2681x; 1.2302x over previous
#include <cuda_runtime.h>
#include <cuda_bf16.h>
#include <mma.h>
#include <cstdint>
#include <math.h>

using namespace nvcuda;

#define B_ROWS 1024
#define D_IN   512
#define D_H    512
#define D_OUT  256

// ---------------- scratch (device globals; no allocation allowed) ----------
__device__ __nv_bfloat16 g_AH[B_ROWS * D_IN];   // activation hi (ping)
__device__ __nv_bfloat16 g_AL[B_ROWS * D_IN];   // activation lo (ping)
__device__ __nv_bfloat16 g_GH[B_ROWS * D_H];    // activation hi (pong)
__device__ __nv_bfloat16 g_GL[B_ROWS * D_H];    // activation lo (pong)
__device__ float         g_H [B_ROWS * D_H];    // pre-LN fp32
__device__ __nv_bfloat16 g_W1H[D_H * D_IN];
__device__ __nv_bfloat16 g_W1L[D_H * D_IN];
__device__ __nv_bfloat16 g_W2H[D_H * D_H];
__device__ __nv_bfloat16 g_W2L[D_H * D_H];
__device__ __nv_bfloat16 g_W3H[D_OUT * D_H];
__device__ __nv_bfloat16 g_W3L[D_OUT * D_H];

// ---------------------------------------------------------------------------
// elementwise: e = exp(v); hi = bf16(e); lo = bf16(e - hi)
// ---------------------------------------------------------------------------
__device__ __forceinline__ void exp_split1(float v, __nv_bfloat16* hi, __nv_bfloat16* lo) {
    float e = __expf(v);
    __nv_bfloat16 h = __float2bfloat16(e);
    *hi = h;
    *lo = __float2bfloat16(e - __bfloat162float(h));
}

// x + all three weight matrices in ONE launch (fewer kernel-duration floors)
__global__ void exp_split_all_kernel(const float* __restrict__ x,
                                     const float* __restrict__ w1,
                                     const float* __restrict__ w2,
                                     const float* __restrict__ w3,
                                     __nv_bfloat16* __restrict__ xh,  __nv_bfloat16* __restrict__ xl,
                                     __nv_bfloat16* __restrict__ w1h, __nv_bfloat16* __restrict__ w1l,
                                     __nv_bfloat16* __restrict__ w2h, __nv_bfloat16* __restrict__ w2l,
                                     __nv_bfloat16* __restrict__ w3h, __nv_bfloat16* __restrict__ w3l) {
    int i = blockIdx.x * blockDim.x + threadIdx.x;
    const int n0 = B_ROWS * D_IN;
    const int n1 = n0 + D_H * D_IN;
    const int n2 = n1 + D_H * D_H;
    const int n3 = n2 + D_OUT * D_H;
    if (i < n0)       exp_split1(x[i],       xh + i,         xl + i);
    else if (i < n1)  exp_split1(w1[i - n0], w1h + (i - n0), w1l + (i - n0));
    else if (i < n2)  exp_split1(w2[i - n1], w2h + (i - n1), w2l + (i - n1));
    else if (i < n3)  exp_split1(w3[i - n2], w3h + (i - n2), w3l + (i - n2));
}

// ---------------------------------------------------------------------------
// WMMA (HMMA) GEMM + log + bias:  C[m,n] = log( sum_k A[m,k]*B[n,k] ) + bias[n]
// A: M x K row-major (hi/lo bf16), B: N x K row-major (hi/lo bf16).
// fp32 accumulate of AhiBhi + AhiBlo + AloBhi.
// CTA tile 128x64, 8 warps 4x2, warp tile 32x32, BK=32 smem-staged.
// REGISTER PREFETCH: 64 CTAs on 148 SMs = 1 CTA/SM, so chunk k+1's LDGs are
// issued before chunk k's MMA section to overlap ~600cyc global latency.
// ---------------------------------------------------------------------------
#define LDA 40          // bf16 ldm for staged 32-wide tiles (8-elem aligned)
#define LDC 68          // f32 ldm for epilogue tile

__global__ __launch_bounds__(256) void gemm_wmma_log_kernel(
    const __nv_bfloat16* __restrict__ Ahi, const __nv_bfloat16* __restrict__ Alo,
    const __nv_bfloat16* __restrict__ Bhi, const __nv_bfloat16* __restrict__ Blo,
    const float* __restrict__ bias, float* __restrict__ C, int N, int K)
{
    extern __shared__ char smem[];
    __nv_bfloat16* sAh = (__nv_bfloat16*)smem;          // 128*LDA
    __nv_bfloat16* sAl = sAh + 128 * LDA;
    __nv_bfloat16* sBh = sAl + 128 * LDA;               // 64*LDA
    __nv_bfloat16* sBl = sBh + 64 * LDA;
    float* sC = (float*)smem;                           // reused in epilogue: 128*LDC

    const int tid = threadIdx.x;
    const int wid = tid >> 5;
    const int bm = blockIdx.y * 128;
    const int bn = blockIdx.x * 64;
    const int wm = (wid >> 1) * 32;      // warp row offset in CTA tile
    const int wn = (wid & 1) * 32;       // warp col offset

    wmma::fragment<wmma::accumulator, 16, 16, 16, float> c[2][2];
#pragma unroll
    for (int i = 0; i < 2; ++i)
#pragma unroll
        for (int j = 0; j < 2; ++j) wmma::fill_fragment(c[i][j], 0.0f);

    const int ar = tid >> 1, ah2 = tid & 1;   // A: row 0..127, 16-col half
    const int br = tid >> 2, bq = tid & 3;    // B: row 0..63, 8-col quarter

    const __nv_bfloat16* gA  = Ahi + (size_t)(bm + ar) * K + ah2 * 16;
    const __nv_bfloat16* gAl = Alo + (size_t)(bm + ar) * K + ah2 * 16;
    const __nv_bfloat16* gB  = Bhi + (size_t)(bn + br) * K + bq * 8;
    const __nv_bfloat16* gBl = Blo + (size_t)(bn + br) * K + bq * 8;

    uint4 rah0, rah1, ral0, ral1, rbh0, rbl0;

    // prefetch chunk 0
    rah0 = *(const uint4*)(gA);
    rah1 = *(const uint4*)(gA + 8);
    ral0 = *(const uint4*)(gAl);
    ral1 = *(const uint4*)(gAl + 8);
    rbh0 = *(const uint4*)(gB);
    rbl0 = *(const uint4*)(gBl);

    for (int k0 = 0; k0 < K; k0 += 32) {
        // registers -> smem
        {
            __nv_bfloat16* dsth = sAh + ar * LDA + ah2 * 16;
            __nv_bfloat16* dstl = sAl + ar * LDA + ah2 * 16;
            *(uint4*)(dsth)     = rah0;
            *(uint4*)(dsth + 8) = rah1;
            *(uint4*)(dstl)     = ral0;
            *(uint4*)(dstl + 8) = ral1;
            *(uint4*)(sBh + br * LDA + bq * 8) = rbh0;
            *(uint4*)(sBl + br * LDA + bq * 8) = rbl0;
        }
        __syncthreads();

        // prefetch next chunk: LDGs overlap the MMA section below
        if (k0 + 32 < K) {
            const int k1 = k0 + 32;
            rah0 = *(const uint4*)(gA  + k1);
            rah1 = *(const uint4*)(gA  + k1 + 8);
            ral0 = *(const uint4*)(gAl + k1);
            ral1 = *(const uint4*)(gAl + k1 + 8);
            rbh0 = *(const uint4*)(gB  + k1);
            rbl0 = *(const uint4*)(gBl + k1);
        }

#pragma unroll
        for (int ks = 0; ks < 32; ks += 16) {
            wmma::fragment<wmma::matrix_a, 16, 16, 16, __nv_bfloat16, wmma::row_major> ahf[2], alf[2];
            wmma::fragment<wmma::matrix_b, 16, 16, 16, __nv_bfloat16, wmma::col_major> bhf[2], blf[2];
#pragma unroll
            for (int i = 0; i < 2; ++i) {
                wmma::load_matrix_sync(ahf[i], sAh + (wm + 16 * i) * LDA + ks, LDA);
                wmma::load_matrix_sync(alf[i], sAl + (wm + 16 * i) * LDA + ks, LDA);
            }
#pragma unroll
            for (int j = 0; j < 2; ++j) {
                wmma::load_matrix_sync(bhf[j], sBh + (wn + 16 * j) * LDA + ks, LDA);
                wmma::load_matrix_sync(blf[j], sBl + (wn + 16 * j) * LDA + ks, LDA);
            }
#pragma unroll
            for (int i = 0; i < 2; ++i)
#pragma unroll
                for (int j = 0; j < 2; ++j) {
                    wmma::mma_sync(c[i][j], ahf[i], bhf[j], c[i][j]);
                    wmma::mma_sync(c[i][j], ahf[i], blf[j], c[i][j]);
                    wmma::mma_sync(c[i][j], alf[i], bhf[j], c[i][j]);
                }
        }
        __syncthreads();   // all frag reads done before next store
    }

#pragma unroll
    for (int i = 0; i < 2; ++i)
#pragma unroll
        for (int j = 0; j < 2; ++j)
            wmma::store_matrix_sync(sC + (wm + 16 * i) * LDC + (wn + 16 * j),
                                    c[i][j], LDC, wmma::mem_row_major);
    __syncthreads();

    {
        const int r = tid >> 1;
        const int h = tid & 1;
        const float* src = sC + r * LDC + h * 32;
        float* dst = C + (size_t)(bm + r) * N + bn + h * 32;
        const float* bi = bias + bn + h * 32;
#pragma unroll
        for (int cidx = 0; cidx < 32; ++cidx)
            dst[cidx] = __logf(src[cidx]) + bi[cidx];
    }
}

// ---------------------------------------------------------------------------
// trop_layernorm via HYBRID shuffle/smem bitonic sort (512 thr = 1 elem/thr).
// 45 bitonic stages: 35 with j<32 are pure __shfl_xor (no barrier); only the
// 10 cross-warp stages (j>=32) touch smem (2 syncs each).
// median=s[255]; q25=s[127]+0.75*(s[128]-s[127]); q75=s[383]+0.25*(s[384]-s[383]);
// then normalize + relu + exp + hi/lo split.
// ---------------------------------------------------------------------------
__global__ __launch_bounds__(512) void ln_relu_expsplit_kernel(
    const float* __restrict__ H, const float* __restrict__ lw,
    const float* __restrict__ lb,
    __nv_bfloat16* __restrict__ Ghi, __nv_bfloat16* __restrict__ Glo)
{
    __shared__ float ss[512];
    const int row = blockIdx.x;
    const int i = threadIdx.x;          // element index 0..511

    const float orig = H[(size_t)row * 512 + i];
    float v = orig;

#pragma unroll
    for (int k = 2; k <= 512; k <<= 1) {
#pragma unroll
        for (int j = k >> 1; j > 0; j >>= 1) {
            const bool up = ((i & k) == 0);
            const bool lower = ((i & j) == 0);
            float p;
            if (j >= 32) {
                ss[i] = v;
                __syncthreads();
                p = ss[i ^ j];
                __syncthreads();
            } else {
                p = __shfl_xor_sync(0xFFFFFFFFu, v, j);
            }
            v = (up == lower) ? fminf(v, p) : fmaxf(v, p);
        }
    }

    ss[i] = v;
    __syncthreads();

    const float med = ss[255];
    const float q25 = fmaf(0.75f, ss[128] - ss[127], ss[127]);
    const float q75 = fmaf(0.25f, ss[384] - ss[383], ss[383]);
    const float inv = 1.0f / fmaxf(q75 - q25, 1e-6f);

    float y = (orig - med) * inv * lw[i] + lb[i];
    y = fmaxf(y, 0.0f);
    exp_split1(y, Ghi + (size_t)row * 512 + i, Glo + (size_t)row * 512 + i);
}

// ---------------------------------------------------------------------------
// launch — inputs: 0:x 1:w1 2:b1 3:ln1_w 4:ln1_b 5:w2 6:b2 7:ln2_w 8:ln2_b 9:w3 10:b3
// ---------------------------------------------------------------------------
extern "C" void kernel_launch(void* const* d_in, const int* in_sizes, int n_in,
                              void* d_out, int out_size)
{
    const float* x     = (const float*)d_in[0];
    const float* w1    = (const float*)d_in[1];
    const float* b1    = (const float*)d_in[2];
    const float* ln1_w = (const float*)d_in[3];
    const float* ln1_b = (const float*)d_in[4];
    const float* w2    = (const float*)d_in[5];
    const float* b2    = (const float*)d_in[6];
    const float* ln2_w = (const float*)d_in[7];
    const float* ln2_b = (const float*)d_in[8];
    const float* w3    = (const float*)d_in[9];
    const float* b3    = (const float*)d_in[10];
    float* out = (float*)d_out;

    __nv_bfloat16 *pAH, *pAL, *pGH, *pGL, *pW1H, *pW1L, *pW2H, *pW2L, *pW3H, *pW3L;
    float* pH;
    cudaGetSymbolAddress((void**)&pAH, g_AH);
    cudaGetSymbolAddress((void**)&pAL, g_AL);
    cudaGetSymbolAddress((void**)&pGH, g_GH);
    cudaGetSymbolAddress((void**)&pGL, g_GL);
    cudaGetSymbolAddress((void**)&pH,  g_H);
    cudaGetSymbolAddress((void**)&pW1H, g_W1H);
    cudaGetSymbolAddress((void**)&pW1L, g_W1L);
    cudaGetSymbolAddress((void**)&pW2H, g_W2H);
    cudaGetSymbolAddress((void**)&pW2L, g_W2L);
    cudaGetSymbolAddress((void**)&pW3H, g_W3H);
    cudaGetSymbolAddress((void**)&pW3L, g_W3L);

    const int SMEM_SZ = 128 * LDC * 4;   // 34816 B (covers stage + epilogue use)
    cudaFuncSetAttribute(gemm_wmma_log_kernel,
                         cudaFuncAttributeMaxDynamicSharedMemorySize, SMEM_SZ);

    // exp-domain operands (hi/lo split), single launch
    {
        int n = B_ROWS * D_IN + D_H * D_IN + D_H * D_H + D_OUT * D_H;
        exp_split_all_kernel<<<(n + 255) / 256, 256>>>(
            x, w1, w2, w3, pAH, pAL, pW1H, pW1L, pW2H, pW2L, pW3H, pW3L);
    }

    // layer 1
    gemm_wmma_log_kernel<<<dim3(D_H / 64, B_ROWS / 128), 256, SMEM_SZ>>>(
        pAH, pAL, pW1H, pW1L, b1, pH, D_H, D_IN);
    ln_relu_expsplit_kernel<<<B_ROWS, 512>>>(pH, ln1_w, ln1_b, pGH, pGL);

    // layer 2
    gemm_wmma_log_kernel<<<dim3(D_H / 64, B_ROWS / 128), 256, SMEM_SZ>>>(
        pGH, pGL, pW2H, pW2L, b2, pH, D_H, D_H);
    ln_relu_expsplit_kernel<<<B_ROWS, 512>>>(pH, ln2_w, ln2_b, pAH, pAL);

    // layer 3 -> output
    gemm_wmma_log_kernel<<<dim3(D_OUT / 64, B_ROWS / 128), 256, SMEM_SZ>>>(
        pAH, pAL, pW3H, pW3L, b3, out, D_OUT, D_H);
}

// round 15
// speedup vs baseline: 1.6231x; 1.2800x over previous
#include <cuda_runtime.h>
#include <cuda_bf16.h>
#include <mma.h>
#include <cstdint>
#include <math.h>

using namespace nvcuda;

#define B_ROWS 1024
#define D_IN   512
#define D_H    512
#define D_OUT  256

// ---------------- scratch (device globals; no allocation allowed) ----------
__device__ __nv_bfloat16 g_AH[B_ROWS * D_IN];
__device__ __nv_bfloat16 g_AL[B_ROWS * D_IN];
__device__ __nv_bfloat16 g_GH[B_ROWS * D_H];
__device__ __nv_bfloat16 g_GL[B_ROWS * D_H];
__device__ float         g_H [B_ROWS * D_H];
__device__ __nv_bfloat16 g_W1H[D_H * D_IN];
__device__ __nv_bfloat16 g_W1L[D_H * D_IN];
__device__ __nv_bfloat16 g_W2H[D_H * D_H];
__device__ __nv_bfloat16 g_W2L[D_H * D_H];
__device__ __nv_bfloat16 g_W3H[D_OUT * D_H];
__device__ __nv_bfloat16 g_W3L[D_OUT * D_H];

// ---------------------------------------------------------------------------
__device__ __forceinline__ void exp_split1(float v, __nv_bfloat16* hi, __nv_bfloat16* lo) {
    float e = __expf(v);
    __nv_bfloat16 h = __float2bfloat16(e);
    *hi = h;
    *lo = __float2bfloat16(e - __bfloat162float(h));
}

__global__ void exp_split_all_kernel(const float* __restrict__ x,
                                     const float* __restrict__ w1,
                                     const float* __restrict__ w2,
                                     const float* __restrict__ w3,
                                     __nv_bfloat16* __restrict__ xh,  __nv_bfloat16* __restrict__ xl,
                                     __nv_bfloat16* __restrict__ w1h, __nv_bfloat16* __restrict__ w1l,
                                     __nv_bfloat16* __restrict__ w2h, __nv_bfloat16* __restrict__ w2l,
                                     __nv_bfloat16* __restrict__ w3h, __nv_bfloat16* __restrict__ w3l) {
    int i = blockIdx.x * blockDim.x + threadIdx.x;
    const int n0 = B_ROWS * D_IN;
    const int n1 = n0 + D_H * D_IN;
    const int n2 = n1 + D_H * D_H;
    const int n3 = n2 + D_OUT * D_H;
    if (i < n0)       exp_split1(x[i],       xh + i,         xl + i);
    else if (i < n1)  exp_split1(w1[i - n0], w1h + (i - n0), w1l + (i - n0));
    else if (i < n2)  exp_split1(w2[i - n1], w2h + (i - n1), w2l + (i - n1));
    else if (i < n3)  exp_split1(w3[i - n2], w3h + (i - n2), w3l + (i - n2));
}

// ---------------------------------------------------------------------------
// WMMA GEMM + log + bias:  C[m,n] = log( sum_k A[m,k]*B[n,k] ) + bias[n]
// hi/lo bf16 split, fp32 accum of AhiBhi + AhiBlo + AloBhi.
// CTA tile 64x64, 128 threads (4 warps, 32x32 warp tile, 2x2 frags).
// BK=64, DOUBLE-BUFFERED smem stages, ONE sync per stage:
//   LDG(s+1) -> compute(s, buf s&1) -> STS(s+1 -> buf (s+1)&1) -> sync
// Grid: 128 CTAs for the 1024x512 layers (87% of 148 SMs vs 43% before).
// ---------------------------------------------------------------------------
#define LDA 72          // bf16 ldm for 64-wide staged tiles (rows 144B apart)
#define LDC 68          // f32 ldm for epilogue tile
#define STAGE_ELEMS (64 * LDA)

__global__ __launch_bounds__(128) void gemm_wmma_log_kernel(
    const __nv_bfloat16* __restrict__ Ahi, const __nv_bfloat16* __restrict__ Alo,
    const __nv_bfloat16* __restrict__ Bhi, const __nv_bfloat16* __restrict__ Blo,
    const float* __restrict__ bias, float* __restrict__ C, int N, int K)
{
    extern __shared__ char smem[];
    __nv_bfloat16* sbase = (__nv_bfloat16*)smem;   // 2 stages x 4 matrices x 64*LDA
    float* sC = (float*)smem;                      // reused in epilogue: 64*LDC

    const int tid = threadIdx.x;
    const int wid = tid >> 5;
    const int bm = blockIdx.y * 64;
    const int bn = blockIdx.x * 64;
    const int wm = (wid >> 1) * 32;      // {0,32}
    const int wn = (wid & 1) * 32;       // {0,32}

    wmma::fragment<wmma::accumulator, 16, 16, 16, float> c[2][2];
#pragma unroll
    for (int i = 0; i < 2; ++i)
#pragma unroll
        for (int j = 0; j < 2; ++j) wmma::fill_fragment(c[i][j], 0.0f);

    // loader: thread t -> row t>>1 (0..63), 32-col half t&1, 4 x uint4 per matrix
    const int lr = tid >> 1;
    const int lh = tid & 1;
    const __nv_bfloat16* gAh = Ahi + (size_t)(bm + lr) * K + lh * 32;
    const __nv_bfloat16* gAl = Alo + (size_t)(bm + lr) * K + lh * 32;
    const __nv_bfloat16* gBh = Bhi + (size_t)(bn + lr) * K + lh * 32;
    const __nv_bfloat16* gBl = Blo + (size_t)(bn + lr) * K + lh * 32;

    uint4 pa[4], pal[4], pb[4], pbl[4];

#define LDG_STAGE(k0) do { \
    _Pragma("unroll") \
    for (int q = 0; q < 4; ++q) { \
        pa[q]  = *(const uint4*)(gAh + (k0) + q * 8); \
        pal[q] = *(const uint4*)(gAl + (k0) + q * 8); \
        pb[q]  = *(const uint4*)(gBh + (k0) + q * 8); \
        pbl[q] = *(const uint4*)(gBl + (k0) + q * 8); \
    } } while (0)

#define STS_STAGE(buf) do { \
    __nv_bfloat16* p = sbase + (buf) * 4 * STAGE_ELEMS + lr * LDA + lh * 32; \
    _Pragma("unroll") \
    for (int q = 0; q < 4; ++q) { \
        *(uint4*)(p + q * 8)                   = pa[q]; \
        *(uint4*)(p + STAGE_ELEMS + q * 8)     = pal[q]; \
        *(uint4*)(p + 2 * STAGE_ELEMS + q * 8) = pb[q]; \
        *(uint4*)(p + 3 * STAGE_ELEMS + q * 8) = pbl[q]; \
    } } while (0)

    const int nst = K >> 6;     // 8 stages for K=512
    LDG_STAGE(0);
    STS_STAGE(0);
    __syncthreads();

    for (int s = 0; s < nst; ++s) {
        if (s + 1 < nst) LDG_STAGE((s + 1) << 6);   // LDGs fly over the MMAs below

        const __nv_bfloat16* sAh = sbase + (s & 1) * 4 * STAGE_ELEMS;
        const __nv_bfloat16* sAl = sAh + STAGE_ELEMS;
        const __nv_bfloat16* sBh = sAh + 2 * STAGE_ELEMS;
        const __nv_bfloat16* sBl = sAh + 3 * STAGE_ELEMS;

#pragma unroll
        for (int ks = 0; ks < 64; ks += 16) {
            wmma::fragment<wmma::matrix_a, 16, 16, 16, __nv_bfloat16, wmma::row_major> ahf[2], alf[2];
            wmma::fragment<wmma::matrix_b, 16, 16, 16, __nv_bfloat16, wmma::col_major> bhf[2], blf[2];
#pragma unroll
            for (int i = 0; i < 2; ++i) {
                wmma::load_matrix_sync(ahf[i], sAh + (wm + 16 * i) * LDA + ks, LDA);
                wmma::load_matrix_sync(alf[i], sAl + (wm + 16 * i) * LDA + ks, LDA);
            }
#pragma unroll
            for (int j = 0; j < 2; ++j) {
                wmma::load_matrix_sync(bhf[j], sBh + (wn + 16 * j) * LDA + ks, LDA);
                wmma::load_matrix_sync(blf[j], sBl + (wn + 16 * j) * LDA + ks, LDA);
            }
#pragma unroll
            for (int i = 0; i < 2; ++i)
#pragma unroll
                for (int j = 0; j < 2; ++j) {
                    wmma::mma_sync(c[i][j], ahf[i], bhf[j], c[i][j]);
                    wmma::mma_sync(c[i][j], ahf[i], blf[j], c[i][j]);
                    wmma::mma_sync(c[i][j], alf[i], bhf[j], c[i][j]);
                }
        }

        if (s + 1 < nst) STS_STAGE((s + 1) & 1);    // other buffer: overlaps peers' MMAs
        __syncthreads();
    }

    // epilogue: frags -> smem (aliases stages; all reads done) -> log+bias -> C
#pragma unroll
    for (int i = 0; i < 2; ++i)
#pragma unroll
        for (int j = 0; j < 2; ++j)
            wmma::store_matrix_sync(sC + (wm + 16 * i) * LDC + (wn + 16 * j),
                                    c[i][j], LDC, wmma::mem_row_major);
    __syncthreads();

    {
        const float* src = sC + lr * LDC + lh * 32;
        float* dst = C + (size_t)(bm + lr) * N + bn + lh * 32;
        const float* bi = bias + bn + lh * 32;
#pragma unroll
        for (int cidx = 0; cidx < 32; ++cidx)
            dst[cidx] = __logf(src[cidx]) + bi[cidx];
    }
}

// ---------------------------------------------------------------------------
// trop_layernorm via hybrid shuffle/smem bitonic sort (validated in R13).
// ---------------------------------------------------------------------------
__global__ __launch_bounds__(512) void ln_relu_expsplit_kernel(
    const float* __restrict__ H, const float* __restrict__ lw,
    const float* __restrict__ lb,
    __nv_bfloat16* __restrict__ Ghi, __nv_bfloat16* __restrict__ Glo)
{
    __shared__ float ss[512];
    const int row = blockIdx.x;
    const int i = threadIdx.x;

    const float orig = H[(size_t)row * 512 + i];
    float v = orig;

#pragma unroll
    for (int k = 2; k <= 512; k <<= 1) {
#pragma unroll
        for (int j = k >> 1; j > 0; j >>= 1) {
            const bool up = ((i & k) == 0);
            const bool lower = ((i & j) == 0);
            float p;
            if (j >= 32) {
                ss[i] = v;
                __syncthreads();
                p = ss[i ^ j];
                __syncthreads();
            } else {
                p = __shfl_xor_sync(0xFFFFFFFFu, v, j);
            }
            v = (up == lower) ? fminf(v, p) : fmaxf(v, p);
        }
    }

    ss[i] = v;
    __syncthreads();

    const float med = ss[255];
    const float q25 = fmaf(0.75f, ss[128] - ss[127], ss[127]);
    const float q75 = fmaf(0.25f, ss[384] - ss[383], ss[383]);
    const float inv = 1.0f / fmaxf(q75 - q25, 1e-6f);

    float y = (orig - med) * inv * lw[i] + lb[i];
    y = fmaxf(y, 0.0f);
    exp_split1(y, Ghi + (size_t)row * 512 + i, Glo + (size_t)row * 512 + i);
}

// ---------------------------------------------------------------------------
// launch — inputs: 0:x 1:w1 2:b1 3:ln1_w 4:ln1_b 5:w2 6:b2 7:ln2_w 8:ln2_b 9:w3 10:b3
// ---------------------------------------------------------------------------
extern "C" void kernel_launch(void* const* d_in, const int* in_sizes, int n_in,
                              void* d_out, int out_size)
{
    const float* x     = (const float*)d_in[0];
    const float* w1    = (const float*)d_in[1];
    const float* b1    = (const float*)d_in[2];
    const float* ln1_w = (const float*)d_in[3];
    const float* ln1_b = (const float*)d_in[4];
    const float* w2    = (const float*)d_in[5];
    const float* b2    = (const float*)d_in[6];
    const float* ln2_w = (const float*)d_in[7];
    const float* ln2_b = (const float*)d_in[8];
    const float* w3    = (const float*)d_in[9];
    const float* b3    = (const float*)d_in[10];
    float* out = (float*)d_out;

    __nv_bfloat16 *pAH, *pAL, *pGH, *pGL, *pW1H, *pW1L, *pW2H, *pW2L, *pW3H, *pW3L;
    float* pH;
    cudaGetSymbolAddress((void**)&pAH, g_AH);
    cudaGetSymbolAddress((void**)&pAL, g_AL);
    cudaGetSymbolAddress((void**)&pGH, g_GH);
    cudaGetSymbolAddress((void**)&pGL, g_GL);
    cudaGetSymbolAddress((void**)&pH,  g_H);
    cudaGetSymbolAddress((void**)&pW1H, g_W1H);
    cudaGetSymbolAddress((void**)&pW1L, g_W1L);
    cudaGetSymbolAddress((void**)&pW2H, g_W2H);
    cudaGetSymbolAddress((void**)&pW2L, g_W2L);
    cudaGetSymbolAddress((void**)&pW3H, g_W3H);
    cudaGetSymbolAddress((void**)&pW3L, g_W3L);

    // smem: 2 stages x 4 matrices x 64*LDA bf16 = 73728 B (epilogue 64*LDC*4 = 17408 aliased)
    const int SMEM_SZ = 2 * 4 * 64 * LDA * 2;
    cudaFuncSetAttribute(gemm_wmma_log_kernel,
                         cudaFuncAttributeMaxDynamicSharedMemorySize, SMEM_SZ);

    // exp-domain operands (hi/lo split), single launch
    {
        int n = B_ROWS * D_IN + D_H * D_IN + D_H * D_H + D_OUT * D_H;
        exp_split_all_kernel<<<(n + 255) / 256, 256>>>(
            x, w1, w2, w3, pAH, pAL, pW1H, pW1L, pW2H, pW2L, pW3H, pW3L);
    }

    // layer 1
    gemm_wmma_log_kernel<<<dim3(D_H / 64, B_ROWS / 64), 128, SMEM_SZ>>>(
        pAH, pAL, pW1H, pW1L, b1, pH, D_H, D_IN);
    ln_relu_expsplit_kernel<<<B_ROWS, 512>>>(pH, ln1_w, ln1_b, pGH, pGL);

    // layer 2
    gemm_wmma_log_kernel<<<dim3(D_H / 64, B_ROWS / 64), 128, SMEM_SZ>>>(
        pGH, pGL, pW2H, pW2L, b2, pH, D_H, D_H);
    ln_relu_expsplit_kernel<<<B_ROWS, 512>>>(pH, ln2_w, ln2_b, pAH, pAL);

    // layer 3 -> output
    gemm_wmma_log_kernel<<<dim3(D_OUT / 64, B_ROWS / 64), 128, SMEM_SZ>>>(
        pAH, pAL, pW3H, pW3L, b3, out, D_OUT, D_H);
}